// round 9
// baseline (speedup 1.0000x reference)
#include <cuda_runtime.h>
#include <cstdint>

#define DIM 64
#define KCODES 1024
#define NROWS (32*64*64)
#define QELEMS (NROWS*DIM)
#define TPB 128
#define UROWS 256
#define NUNITS 1024            // 512 row-tiles x 2 code-halves
#define NSM 148

// smem float-word layout
#define XST 256
#define XS_W (64*XST)          // 16384 words per x buf
#define OFF_XS 0               // 2 bufs
#define OFF_EB 32768           // 2 bufs x 4096 words
#define EB_W 4096
#define OFF_SE 40960           // 2048 words (se dup)
#define OFF_MS 43008
#define SMEM_W (OFF_MS + 8)

typedef unsigned long long u64;

__device__ float2 g_dup[KCODES][DIM];   // (e,e)
__device__ float2 g_se2[KCODES];        // (se,se)
__device__ float2 g_half0[NROWS];
__device__ float2 g_half1[NROWS];
__device__ float g_losspart[512];
__device__ int g_ctr;

__device__ __forceinline__ uint32_t s2u(const void* p){
    uint32_t a; asm("{ .reg .u64 t; cvta.to.shared.u64 t, %1; cvt.u32.u64 %0, t; }":"=r"(a):"l"(p)); return a;
}
__device__ __forceinline__ void fma2(u64& acc, u64 a, u64 b) {
    asm("fma.rn.f32x2 %0, %1, %2, %3;" : "=l"(acc) : "l"(a), "l"(b), "l"(acc));
}
__device__ __forceinline__ u64 add2(u64 a, u64 b){ u64 d; asm("add.rn.f32x2 %0,%1,%2;":"=l"(d):"l"(a),"l"(b)); return d; }
__device__ __forceinline__ u64 mul2(u64 a, u64 b){ u64 d; asm("mul.rn.f32x2 %0,%1,%2;":"=l"(d):"l"(a),"l"(b)); return d; }
__device__ __forceinline__ void unpack2(u64 v, float& lo, float& hi){
    unsigned a, b; asm("mov.b64 {%0,%1}, %2;" : "=r"(a), "=r"(b) : "l"(v));
    lo = __uint_as_float(a); hi = __uint_as_float(b);
}
__device__ __forceinline__ u64 bcast2(float x){
    u64 d; unsigned r = __float_as_uint(x);
    asm("mov.b64 %0, {%1,%1};" : "=l"(d) : "r"(r)); return d;
}
#define CPA16(dst, src) asm volatile("cp.async.cg.shared.global [%0], [%1], 16;"::"r"(dst),"l"(src):"memory")
#define CPCOMMIT()      asm volatile("cp.async.commit_group;":::"memory")
#define CPWAIT(n)       asm volatile("cp.async.wait_group %0;"::"n"(n):"memory")

// ---------------- prep -----------------------------------------------------
__global__ void vq_prep(const float* __restrict__ cb) {
    int k = blockIdx.x * blockDim.x + threadIdx.x;
    if (k == 0) g_ctr = 0;
    if (k >= KCODES) return;
    float s = 0.f;
#pragma unroll
    for (int c = 0; c < DIM; ++c) {
        float v = cb[k*DIM + c];
        s = fmaf(v, v, s);
        g_dup[k][c] = make_float2(v, v);
    }
    g_se2[k] = make_float2(s, s);
}

// ---------------- persistent scan ------------------------------------------
#define ISSUE_X(uu, bf) do { int _t = (uu) >> 1; int _n0 = _t * UROWS; \
    int _b = _n0 >> 12, _hw = _n0 & 4095; \
    const char* _src = (const char*)(x + (size_t)_b*262144 + _hw); \
    for (int g = tid; g < 4096; g += TPB) { int _ch = g >> 6, _r4 = (g & 63) << 2; \
        CPA16(sb + 4*(OFF_XS + (bf)*XS_W + _ch*XST + _r4), _src + (size_t)_ch*16384 + _r4*4); } } while (0)

#define ISSUE_E(uu, j) do { const char* _s = (const char*)g_dup + ((size_t)(((uu)&1)*512 + (j)*32))*512; \
    for (int g = tid; g < 1024; g += TPB) \
        CPA16(sb + 4*(OFF_EB + ((j)&1)*EB_W) + g*16, _s + g*16); } while (0)

__global__ __launch_bounds__(TPB, 1) void vq_scan(const float* __restrict__ x) {
    extern __shared__ float sm[];
    const uint32_t sb = s2u(sm);
    const int tid = threadIdx.x;
    int* ms = (int*)(sm + OFF_MS);
    const u64 NEG2 = bcast2(-2.0f);

    for (int i = tid; i < 2048; i += TPB) sm[OFF_SE + i] = ((const float*)g_se2)[i];

    if (tid == 0) ms[0] = atomicAdd(&g_ctr, 1);
    __syncthreads();
    int u = ms[0], p = 0, nu = NUNITS;
    if (u < NUNITS) {
        ISSUE_X(u, 0); ISSUE_E(u, 0); CPCOMMIT();
        ISSUE_E(u, 1); CPCOMMIT();
    }

    while (u < NUNITS) {
        const int k0 = (u & 1) * 512;
        u64 sx2 = 0ull;
        float best0 = 3e38f, best1 = 3e38f;
        int bk0 = 0, bk1 = 0;

        for (int c = 0; c < 16; ++c) {
            CPWAIT(1);
            __syncthreads();
            const float* xs = sm + OFF_XS + p*XS_W + 2*tid;
            const float* eb = sm + OFF_EB + (c & 1)*EB_W;

            if (c == 0) {
                sx2 = 0ull;
#pragma unroll 1
                for (int c4 = 0; c4 < 16; ++c4) {
                    const float* xc = xs + c4*4*XST;
                    u64 x0 = *(const u64*)(xc);
                    u64 x1 = *(const u64*)(xc + XST);
                    u64 x2 = *(const u64*)(xc + 2*XST);
                    u64 x3 = *(const u64*)(xc + 3*XST);
                    fma2(sx2, x0, x0); fma2(sx2, x1, x1);
                    fma2(sx2, x2, x2); fma2(sx2, x3, x3);
                }
            }

            u64 acc[32];
#pragma unroll
            for (int kk = 0; kk < 32; ++kk) acc[kk] = 0ull;

#pragma unroll 1
            for (int c4 = 0; c4 < 16; ++c4) {
                const float* xc = xs + c4*4*XST;
                u64 x0 = *(const u64*)(xc);
                u64 x1 = *(const u64*)(xc + XST);
                u64 x2 = *(const u64*)(xc + 2*XST);
                u64 x3 = *(const u64*)(xc + 3*XST);
#pragma unroll
                for (int kk = 0; kk < 32; ++kk) {
                    const float4* e4 = (const float4*)(eb + kk*128 + c4*8);
                    float4 f0 = e4[0], f1 = e4[1];
                    const u64* p0 = (const u64*)&f0;
                    const u64* p1 = (const u64*)&f1;
                    fma2(acc[kk], x0, p0[0]);
                    fma2(acc[kk], x1, p0[1]);
                    fma2(acc[kk], x2, p1[0]);
                    fma2(acc[kk], x3, p1[1]);
                }
            }

            const int kbase = k0 + c*32;
#pragma unroll
            for (int kk = 0; kk < 32; ++kk) {
                u64 sep = *(const u64*)(sm + OFF_SE + (kbase + kk)*2);
                u64 d2 = add2(add2(sx2, sep), mul2(NEG2, acc[kk]));
                float dl, dh; unpack2(d2, dl, dh);
                if (dl < best0) { best0 = dl; bk0 = kbase + kk; }
                if (dh < best1) { best1 = dh; bk1 = kbase + kk; }
            }

            if (c == 13 && tid == 0) ms[1] = atomicAdd(&g_ctr, 1);
            __syncthreads();

            if (c <= 13) { ISSUE_E(u, c + 2); CPCOMMIT(); }
            else if (c == 14) {
                nu = ms[1];
                if (nu < NUNITS) { ISSUE_X(nu, p ^ 1); ISSUE_E(nu, 0); }
                CPCOMMIT();
            } else {
                if (nu < NUNITS) ISSUE_E(nu, 1);
                CPCOMMIT();
            }
        }

        float2* dst = (u & 1) ? g_half1 : g_half0;
        const int n0w = (u >> 1) * UROWS;
        dst[n0w + 2*tid]     = make_float2(best0, (float)bk0);
        dst[n0w + 2*tid + 1] = make_float2(best1, (float)bk1);
        p ^= 1;
        u = nu;
    }
}

// ---------------- merge + gather + loss ------------------------------------
__global__ __launch_bounds__(256) void vq_merge(const float* __restrict__ x,
                                                const float* __restrict__ cb,
                                                float* __restrict__ out) {
    __shared__ float red[256];
    const int tid = threadIdx.x;
    const int n = blockIdx.x*256 + tid;

    float2 h0 = g_half0[n];
    float2 h1 = g_half1[n];
    int code = (h1.x < h0.x) ? (int)h1.y : (int)h0.y;   // tie -> half0 (smaller k)

    const int b = n >> 12, hw = n & 4095;
    const float* xr = x + (size_t)b*262144 + hw;
    const float* e  = cb + code*DIM;
    float* q = out + 1 + (size_t)b*262144 + hw;
    float lsum = 0.f;
#pragma unroll
    for (int c = 0; c < DIM; ++c) {
        float ec = __ldg(e + c);
        float d = ec - xr[c*4096];
        lsum = fmaf(d, d, lsum);
        q[c*4096] = ec;
    }
    out[1 + QELEMS + n] = (float)code;

    red[tid] = lsum;
    __syncthreads();
#pragma unroll
    for (int s = 128; s > 0; s >>= 1) {
        if (tid < s) red[tid] += red[tid + s];
        __syncthreads();
    }
    if (tid == 0) g_losspart[blockIdx.x] = red[0];
}

__global__ void vq_loss(float* __restrict__ out) {
    __shared__ float red[512];
    int tid = threadIdx.x;
    red[tid] = g_losspart[tid];
    __syncthreads();
    for (int s = 256; s > 0; s >>= 1) {
        if (tid < s) red[tid] += red[tid + s];
        __syncthreads();
    }
    if (tid == 0) out[0] = red[0] * (1.25f / (float)QELEMS);
}

extern "C" void kernel_launch(void* const* d_in, const int* in_sizes, int n_in,
                              void* d_out, int out_size) {
    const float* x  = (const float*)d_in[0];
    const float* cb = (const float*)d_in[1];
    float* out = (float*)d_out;
    cudaFuncSetAttribute(vq_scan, cudaFuncAttributeMaxDynamicSharedMemorySize, SMEM_W*4);
    vq_prep<<<4, 256>>>(cb);
    vq_scan<<<NSM, TPB, SMEM_W*4>>>(x);
    vq_merge<<<NROWS/256, 256>>>(x, cb, out);
    vq_loss<<<1, 512>>>(out);
}

// round 11
// speedup vs baseline: 1.3867x; 1.3867x over previous
#include <cuda_runtime.h>
#include <cstdint>

// VQ-VAE quantizer — bit-faithful fp32 argmin, FFMA2 mainloop.
// R10 resubmit: TPB=256 (2 warps/SMSP), 2 rows/thread, 256 CTAs, 1 CTA/SM.
// out f32: [ loss(1) | quantized NCHW (8388608) | idx (131072) ]

#define TPB 256
#define RPB 512
#define RSTRIDE 68
#define DIM 64
#define KCODES 1024
#define NROWS (32*64*64)
#define NB (NROWS/RPB)          // 256 CTAs
#define QELEMS (NROWS*DIM)

// smem words
#define XS_W 0                  // 512*68 = 34816
#define ES_W 34816              // 2 bufs x 4096
#define SES_W 43008             // 1024
#define RED_W 44032             // 256
#define SMEM_B ((RED_W + 256) * 4)

__device__ float g_se[KCODES];
__device__ float g_pair[KCODES/2][128];  // [k>>1][c*2 + (k&1)] = cb[k][c]
__device__ float g_losspart[NB];

typedef unsigned long long u64;
__device__ __forceinline__ uint32_t s2u(const void* p){
    uint32_t a; asm("{ .reg .u64 t; cvta.to.shared.u64 t, %1; cvt.u32.u64 %0, t; }":"=r"(a):"l"(p)); return a;
}
__device__ __forceinline__ void fma2(u64& acc, u64 a, u64 b) {
    asm("fma.rn.f32x2 %0, %1, %2, %3;" : "=l"(acc) : "l"(a), "l"(b), "l"(acc));
}
__device__ __forceinline__ u64 bcast2(float x) {
    u64 d; unsigned r = __float_as_uint(x);
    asm("mov.b64 %0, {%1,%1};" : "=l"(d) : "r"(r));
    return d;
}
__device__ __forceinline__ void unpack2(u64 v, float& lo, float& hi) {
    unsigned a, b;
    asm("mov.b64 {%0,%1}, %2;" : "=r"(a), "=r"(b) : "l"(v));
    lo = __uint_as_float(a); hi = __uint_as_float(b);
}
#define CPA16(dst, src) asm volatile("cp.async.cg.shared.global [%0], [%1], 16;"::"r"(dst),"l"(src):"memory")
#define CPCOMMIT()      asm volatile("cp.async.commit_group;":::"memory")
#define CPWAIT(n)       asm volatile("cp.async.wait_group %0;"::"n"(n):"memory")

// ---------------- prep: se + pair-interleaved codebook ---------------------
__global__ void vq_prep(const float* __restrict__ cb) {
    int k = blockIdx.x * blockDim.x + threadIdx.x;
    if (k >= KCODES) return;
    float s = 0.f;
#pragma unroll
    for (int c = 0; c < DIM; ++c) {
        float v = cb[k*DIM + c];
        s = fmaf(v, v, s);
        g_pair[k >> 1][c*2 + (k & 1)] = v;
    }
    g_se[k] = s;
}

// ---------------- main ------------------------------------------------------
__global__ __launch_bounds__(TPB, 1) void vq_main(const float* __restrict__ x,
                                                  const float* __restrict__ cb,
                                                  float* __restrict__ out) {
    extern __shared__ float sm[];
    const uint32_t sb = s2u(sm);
    const int tid = threadIdx.x;
    const int n0 = blockIdx.x * RPB;
    const int b = n0 >> 12, off = n0 & 4095;
    const float* xb = x + (size_t)b*262144 + off;

#define BLOAD(ch) do { int _bf = (ch) & 1; \
    for (int i = tid; i < 1024; i += TPB) \
        CPA16(sb + 4*(ES_W + _bf*4096 + i*4), (const char*)g_pair + (ch)*16384 + i*16); \
    CPCOMMIT(); } while (0)

    BLOAD(0);

    // x tile -> smem [r][c] stride 68 (coalesced float4 over rows)
    for (int i = tid; i < DIM * (RPB/4); i += TPB) {
        int c = i >> 7, r4 = (i & 127) << 2;
        float4 v = *reinterpret_cast<const float4*>(xb + c*4096 + r4);
        sm[XS_W + (r4+0)*RSTRIDE + c] = v.x;
        sm[XS_W + (r4+1)*RSTRIDE + c] = v.y;
        sm[XS_W + (r4+2)*RSTRIDE + c] = v.z;
        sm[XS_W + (r4+3)*RSTRIDE + c] = v.w;
    }
    for (int i = tid; i < KCODES; i += TPB) sm[SES_W + i] = g_se[i];
    BLOAD(1);
    __syncthreads();

    // per-row |x|^2
    float sx[2];
#pragma unroll
    for (int j = 0; j < 2; ++j) {
        const float* xr = sm + XS_W + (tid + j*TPB)*RSTRIDE;
        float s = 0.f;
#pragma unroll
        for (int c = 0; c < DIM; ++c) s = fmaf(xr[c], xr[c], s);
        sx[j] = s;
    }

    float best[2] = {3e38f, 3e38f};
    int bidx[2] = {0, 0};

    for (int cc = 0; cc < 16; ++cc) {
        int buf = cc & 1;
        CPWAIT(1);
        __syncthreads();
        const float* eb = sm + ES_W + buf*4096;

        for (int kg = 0; kg < 4; ++kg) {
            u64 acc[2][8];
#pragma unroll
            for (int j = 0; j < 2; ++j)
#pragma unroll
                for (int p = 0; p < 8; ++p) acc[j][p] = 0ull;

#pragma unroll 4
            for (int c4 = 0; c4 < 16; ++c4) {
                u64 a[2][4];
#pragma unroll
                for (int j = 0; j < 2; ++j) {
                    float4 xa = *reinterpret_cast<const float4*>(
                        sm + XS_W + (tid + j*TPB)*RSTRIDE + c4*4);
                    a[j][0] = bcast2(xa.x); a[j][1] = bcast2(xa.y);
                    a[j][2] = bcast2(xa.z); a[j][3] = bcast2(xa.w);
                }
#pragma unroll
                for (int p = 0; p < 8; ++p) {
                    const u64* ep = reinterpret_cast<const u64*>(eb + (kg*8+p)*128 + c4*8);
                    ulonglong2 eA = *reinterpret_cast<const ulonglong2*>(ep);
                    ulonglong2 eB = *reinterpret_cast<const ulonglong2*>(ep + 2);
#pragma unroll
                    for (int j = 0; j < 2; ++j) {
                        fma2(acc[j][p], a[j][0], eA.x); fma2(acc[j][p], a[j][1], eA.y);
                        fma2(acc[j][p], a[j][2], eB.x); fma2(acc[j][p], a[j][3], eB.y);
                    }
                }
            }
#pragma unroll
            for (int p = 0; p < 8; ++p) {
                int ke = cc*64 + kg*16 + 2*p;
                float2 se2 = *reinterpret_cast<const float2*>(sm + SES_W + ke);
#pragma unroll
                for (int j = 0; j < 2; ++j) {
                    float Pe, Po;
                    unpack2(acc[j][p], Pe, Po);
                    float de = __fadd_rn(__fadd_rn(sx[j], se2.x), __fmul_rn(-2.0f, Pe));
                    float dd = __fadd_rn(__fadd_rn(sx[j], se2.y), __fmul_rn(-2.0f, Po));
                    if (de < best[j]) { best[j] = de; bidx[j] = ke; }
                    if (dd < best[j]) { best[j] = dd; bidx[j] = ke + 1; }
                }
            }
        }
        __syncthreads();
        if (cc + 2 < 16) BLOAD(cc + 2);
    }

    // epilogue: gather q (NCHW coalesced per c), idx, loss
    float lsum = 0.f;
    float* qout = out + 1;
    float* iout = out + 1 + QELEMS;
#pragma unroll 1
    for (int j = 0; j < 2; ++j) {
        int row = tid + j*TPB;
        int code = bidx[j];
        const float* e = cb + code*DIM;
        float* q = qout + (size_t)b*262144 + off + row;
#pragma unroll
        for (int c = 0; c < DIM; ++c) {
            float ec = __ldg(e + c);
            float d = ec - sm[XS_W + row*RSTRIDE + c];
            lsum = fmaf(d, d, lsum);
            q[c*4096] = ec;
        }
        iout[n0 + row] = (float)code;
    }

    float* red = sm + RED_W;
    red[tid] = lsum;
    __syncthreads();
#pragma unroll
    for (int s = TPB/2; s > 0; s >>= 1) {
        if (tid < s) red[tid] += red[tid + s];
        __syncthreads();
    }
    if (tid == 0) g_losspart[blockIdx.x] = red[0];
}

__global__ void vq_loss(float* __restrict__ out) {
    __shared__ float red[NB];
    int tid = threadIdx.x;
    red[tid] = g_losspart[tid];
    __syncthreads();
    for (int s = NB/2; s > 0; s >>= 1) {
        if (tid < s) red[tid] += red[tid + s];
        __syncthreads();
    }
    if (tid == 0) out[0] = red[0] * (1.25f / (float)QELEMS);
}

extern "C" void kernel_launch(void* const* d_in, const int* in_sizes, int n_in,
                              void* d_out, int out_size) {
    const float* x  = (const float*)d_in[0];
    const float* cb = (const float*)d_in[1];
    float* out = (float*)d_out;
    cudaFuncSetAttribute(vq_main, cudaFuncAttributeMaxDynamicSharedMemorySize, SMEM_B);
    vq_prep<<<4, 256>>>(cb);
    vq_main<<<NB, TPB, SMEM_B>>>(x, cb, out);
    vq_loss<<<1, NB>>>(out);
}